// round 9
// baseline (speedup 1.0000x reference)
#include <cuda_runtime.h>
#include <cstdint>

using ull = unsigned long long;

#define THREADS 256
#define TILE    512            // 2 edges per thread (one f32x2 pack)
#define HID     10
#define NOUT    19
#define ST_FLOATS (TILE * NOUT)          // 9728 floats
#define ST_BYTES  (ST_FLOATS * 4)        // 38912 bytes
#define NWT       259                    // 40 W1 + 10 b1 + 190 W2 + 19 b2 (packed pairs)

// packed weight bank: [0,40) W1p[j*4+r], [40,50) b1p, [50,240) W2p[k*10+j], [240,259) b2p
__device__   ull gWt[NWT];
__constant__ ull cWt[NWT];

// ---------- packed f32x2 helpers ----------
__device__ __forceinline__ ull pack2(float lo, float hi) {
    ull r; asm("mov.b64 %0, {%1, %2};" : "=l"(r) : "f"(lo), "f"(hi)); return r;
}
__device__ __forceinline__ void unpack2(ull v, float& lo, float& hi) {
    asm("mov.b64 {%0, %1}, %2;" : "=f"(lo), "=f"(hi) : "l"(v));
}
__device__ __forceinline__ ull ffma2(ull a, ull b, ull c) {
    ull d; asm("fma.rn.f32x2 %0, %1, %2, %3;" : "=l"(d) : "l"(a), "l"(b), "l"(c)); return d;
}
__device__ __forceinline__ ull add2(ull a, ull b) {
    ull d; asm("add.rn.f32x2 %0, %1, %2;" : "=l"(d) : "l"(a), "l"(b)); return d;
}
__device__ __forceinline__ ull relu2(ull a) {
    float lo, hi; unpack2(a, lo, hi);
    return pack2(fmaxf(lo, 0.0f), fmaxf(hi, 0.0f));
}

// ---- prep: pack duplicated (w,w) pairs into gWt (then D2D-copied to cWt) ----
__global__ void pack_weights_kernel(const float* __restrict__ W1,
                                    const float* __restrict__ b1,
                                    const float* __restrict__ W2,
                                    const float* __restrict__ b2)
{
    int t = threadIdx.x;
    if (t < 40) {                       // W1p[j*4+r] = (W1[r][j], W1[r][j])
        int j = t >> 2, r = t & 3;
        float w = W1[r * 10 + j];
        gWt[t] = pack2(w, w);
    } else if (t < 50) {
        float v = b1[t - 40];  gWt[t] = pack2(v, v);
    } else if (t < 240) {               // W2p[k*10+j] = (W2[j][k], W2[j][k])
        int q = t - 50; int k = q / 10, j = q - k * 10;
        float w = W2[j * NOUT + k];
        gWt[t] = pack2(w, w);
    } else if (t < NWT) {
        float v = b2[t - 240]; gWt[t] = pack2(v, v);
    }
}

__global__ __launch_bounds__(THREADS, 3)
void edge_mlp_kernel(const float* __restrict__ src,
                     const float* __restrict__ dest,
                     const float* __restrict__ ea,
                     const float* __restrict__ u,
                     const int* __restrict__ batch,  // int32 graph ids
                     float* __restrict__ out,        // (E,19)
                     int E, int B, int nTiles)
{
    extern __shared__ __align__(16) char smem[];
    float* st = (float*)smem;                               // [512*19] staging
    float* su = (float*)(smem + ST_BYTES);                  // [B] u table

    const int tid = threadIdx.x;
    const int Bm1 = B - 1;

    for (int i = tid; i < B; i += THREADS) su[i] = u[i];
    __syncthreads();

    const int stride = gridDim.x;

    // ---- software pipeline: raw input regs for the *current* tile ----
    float cs0, cs1, cd0, cd1, ca0, ca1;
    int   ci0, ci1;

    int tile = blockIdx.x;
    bool curFull = (tile < nTiles) && ((tile * TILE + TILE) <= E);
    if (curFull) {
        const int g0 = tile * TILE + tid;
        const int g1 = g0 + THREADS;
        cs0 = src[g0];  cs1 = src[g1];
        cd0 = dest[g0]; cd1 = dest[g1];
        ca0 = ea[g0];   ca1 = ea[g1];
        ci0 = batch[g0]; ci1 = batch[g1];
    }

    for (; tile < nTiles; tile += stride) {
        const int base = tile * TILE;
        const int nextTile = tile + stride;
        const bool nextFull = (nextTile < nTiles) && ((nextTile * TILE + TILE) <= E);

        if (curFull) {
            // ---- consume raw regs into packed operands (u gathered now) ----
            int i0 = min(max(ci0, 0), Bm1);
            int i1 = min(max(ci1, 0), Bm1);
            ull S = pack2(cs0, cs1);
            ull D = pack2(cd0, cd1);
            ull A = pack2(ca0, ca1);
            ull U = pack2(su[i0], su[i1]);

            // ---- prefetch next tile's raw inputs (hidden under the MLP) ----
            if (nextFull) {
                const int g0 = nextTile * TILE + tid;
                const int g1 = g0 + THREADS;
                cs0 = src[g0];  cs1 = src[g1];
                cd0 = dest[g0]; cd1 = dest[g1];
                ca0 = ea[g0];   ca1 = ea[g1];
                ci0 = batch[g0]; ci1 = batch[g1];
            }

            // ---- stage 1: h = relu(x @ W1 + b1); weights from constant bank ----
            ull h[HID];
            #pragma unroll
            for (int j = 0; j < HID; j++) {
                ull acc = ffma2(S, cWt[j * 4 + 0], cWt[40 + j]);
                acc = ffma2(D, cWt[j * 4 + 1], acc);
                acc = ffma2(A, cWt[j * 4 + 2], acc);
                acc = ffma2(U, cWt[j * 4 + 3], acc);
                h[j] = relu2(acc);
            }

            // ---- stage 2: out = h @ W2 + b2; constants, even/odd dual chains ----
            #pragma unroll
            for (int k = 0; k < NOUT; k++) {
                ull accA = ffma2(h[0], cWt[50 + k * 10 + 0], cWt[240 + k]);
                ull accB = ffma2(h[1], cWt[50 + k * 10 + 1], 0ULL);
                accA = ffma2(h[2], cWt[50 + k * 10 + 2], accA);
                accB = ffma2(h[3], cWt[50 + k * 10 + 3], accB);
                accA = ffma2(h[4], cWt[50 + k * 10 + 4], accA);
                accB = ffma2(h[5], cWt[50 + k * 10 + 5], accB);
                accA = ffma2(h[6], cWt[50 + k * 10 + 6], accA);
                accB = ffma2(h[7], cWt[50 + k * 10 + 7], accB);
                accA = ffma2(h[8], cWt[50 + k * 10 + 8], accA);
                accB = ffma2(h[9], cWt[50 + k * 10 + 9], accB);
                ull acc = add2(accA, accB);
                float lo, hi; unpack2(acc, lo, hi);
                st[tid * NOUT + k]             = lo;   // stride 19: conflict-free
                st[(tid + THREADS) * NOUT + k] = hi;
            }
            __syncthreads();

            // ---- coalesced float4 flush: 512*19 floats = 2432 float4 ----
            float4* o4 = (float4*)(out + (size_t)base * NOUT);
            const float4* s4 = (const float4*)st;
            #pragma unroll
            for (int q = 0; q < ST_FLOATS / 4 / THREADS + 1; q++) {
                int idx = q * THREADS + tid;
                if (idx < ST_FLOATS / 4) o4[idx] = s4[idx];
            }
            __syncthreads();
        } else {
            // -------- tail tile (never hit when E % 512 == 0) --------
            const float* cf = (const float*)cWt;   // lo halves of packed pairs
            #pragma unroll
            for (int half = 0; half < 2; half++) {
                int row = tid + half * THREADS;
                int g = base + row;
                if (g < E) {
                    float s = src[g], d = dest[g], a = ea[g];
                    int bi = min(max(batch[g], 0), Bm1);
                    float uu = su[bi];
                    float h[HID];
                    #pragma unroll
                    for (int j = 0; j < HID; j++) {
                        float acc = cf[(40 + j) * 2];
                        acc = fmaf(s,  cf[(j * 4 + 0) * 2], acc);
                        acc = fmaf(d,  cf[(j * 4 + 1) * 2], acc);
                        acc = fmaf(a,  cf[(j * 4 + 2) * 2], acc);
                        acc = fmaf(uu, cf[(j * 4 + 3) * 2], acc);
                        h[j] = fmaxf(acc, 0.0f);
                    }
                    #pragma unroll
                    for (int k = 0; k < NOUT; k++) {
                        float acc = cf[(240 + k) * 2];
                        #pragma unroll
                        for (int j = 0; j < HID; j++)
                            acc = fmaf(h[j], cf[(50 + k * HID + j) * 2], acc);
                        st[row * NOUT + k] = acc;
                    }
                }
            }
            __syncthreads();
            int ve = E - base; if (ve > TILE) ve = TILE;
            size_t obase = (size_t)base * NOUT;
            for (int q = tid; q < ve * NOUT; q += THREADS) out[obase + q] = st[q];
            __syncthreads();

            if (nextFull) {
                const int g0 = nextTile * TILE + tid;
                const int g1 = g0 + THREADS;
                cs0 = src[g0];  cs1 = src[g1];
                cd0 = dest[g0]; cd1 = dest[g1];
                ca0 = ea[g0];   ca1 = ea[g1];
                ci0 = batch[g0]; ci1 = batch[g1];
            }
        }
        curFull = nextFull;
    }
}

extern "C" void kernel_launch(void* const* d_in, const int* in_sizes, int n_in,
                              void* d_out, int out_size)
{
    const float* src   = (const float*)d_in[0];
    const float* dest  = (const float*)d_in[1];
    const float* ea    = (const float*)d_in[2];
    const float* u     = (const float*)d_in[3];
    const int*   batch = (const int*)d_in[4];      // int32
    const float* W1    = (const float*)d_in[5];
    const float* b1    = (const float*)d_in[6];
    const float* W2    = (const float*)d_in[7];
    const float* b2    = (const float*)d_in[8];
    float* out = (float*)d_out;

    const int E = in_sizes[0];
    const int B = in_sizes[3];
    const int nTiles = (E + TILE - 1) / TILE;

    // 1) pack duplicated weight pairs into gWt (device global)
    pack_weights_kernel<<<1, 288>>>(W1, b1, W2, b2);

    // 2) D2D copy into the constant bank (capture-legal async memcpy node)
    void* gptr = nullptr;
    cudaGetSymbolAddress(&gptr, gWt);
    cudaMemcpyToSymbolAsync(cWt, gptr, NWT * sizeof(ull), 0,
                            cudaMemcpyDeviceToDevice);

    // 3) main kernel: 3 CTAs/SM resident
    const int ub = (B * 4 + 15) & ~15;
    const int smemBytes = ST_BYTES + ub + 16;

    cudaFuncSetAttribute(edge_mlp_kernel,
                         cudaFuncAttributeMaxDynamicSharedMemorySize, smemBytes);

    int grid = nTiles < 444 ? nTiles : 444;   // 148 SMs * 3 CTAs
    if (grid < 1) grid = 1;

    edge_mlp_kernel<<<grid, THREADS, smemBytes>>>(
        src, dest, ea, u, batch, out, E, B, nTiles);
}

// round 15
// speedup vs baseline: 1.5553x; 1.5553x over previous
#include <cuda_runtime.h>
#include <cstdint>

using ull = unsigned long long;

#define THREADS 256
#define PACKS   2              // f32x2 packs per thread (2 edges each) -> 4 edges/thread
#define TILE    1024           // THREADS * 2 * PACKS
#define HID     10
#define NOUT    19
#define ST_FLOATS (TILE * NOUT)          // 19456 floats
#define ST_BYTES  (ST_FLOATS * 4)        // 77824 bytes (multiple of 16)
#define NWT       259                    // 40 W1 + 10 b1 + 190 W2 + 19 b2 (packed pairs)

// packed weight bank: [0,40) W1p[j*4+r], [40,50) b1p, [50,240) W2p[k*10+j], [240,259) b2p
__device__   ull gWt[NWT];
__constant__ ull cWt[NWT];

// ---------- packed f32x2 helpers ----------
__device__ __forceinline__ ull pack2(float lo, float hi) {
    ull r; asm("mov.b64 %0, {%1, %2};" : "=l"(r) : "f"(lo), "f"(hi)); return r;
}
__device__ __forceinline__ void unpack2(ull v, float& lo, float& hi) {
    asm("mov.b64 {%0, %1}, %2;" : "=f"(lo), "=f"(hi) : "l"(v));
}
__device__ __forceinline__ ull ffma2(ull a, ull b, ull c) {
    ull d; asm("fma.rn.f32x2 %0, %1, %2, %3;" : "=l"(d) : "l"(a), "l"(b), "l"(c)); return d;
}
__device__ __forceinline__ ull add2(ull a, ull b) {
    ull d; asm("add.rn.f32x2 %0, %1, %2;" : "=l"(d) : "l"(a), "l"(b)); return d;
}
__device__ __forceinline__ ull relu2(ull a) {
    float lo, hi; unpack2(a, lo, hi);
    return pack2(fmaxf(lo, 0.0f), fmaxf(hi, 0.0f));
}
__device__ __forceinline__ uint32_t smem_u32(const void* p) {
    uint32_t a;
    asm("{ .reg .u64 t; cvta.to.shared.u64 t, %1; cvt.u32.u64 %0, t; }" : "=r"(a) : "l"(p));
    return a;
}

// ---- prep: pack duplicated (w,w) pairs into gWt (then D2D-copied to cWt) ----
__global__ void pack_weights_kernel(const float* __restrict__ W1,
                                    const float* __restrict__ b1,
                                    const float* __restrict__ W2,
                                    const float* __restrict__ b2)
{
    int t = threadIdx.x;
    if (t < 40) {                       // W1p[j*4+r] = (W1[r][j], W1[r][j])
        int j = t >> 2, r = t & 3;
        float w = W1[r * 10 + j];
        gWt[t] = pack2(w, w);
    } else if (t < 50) {
        float v = b1[t - 40];  gWt[t] = pack2(v, v);
    } else if (t < 240) {               // W2p[k*10+j] = (W2[j][k], W2[j][k])
        int q = t - 50; int k = q / 10, j = q - k * 10;
        float w = W2[j * NOUT + k];
        gWt[t] = pack2(w, w);
    } else if (t < NWT) {
        float v = b2[t - 240]; gWt[t] = pack2(v, v);
    }
}

__global__ __launch_bounds__(THREADS, 2)
void edge_mlp_kernel(const float* __restrict__ src,
                     const float* __restrict__ dest,
                     const float* __restrict__ ea,
                     const float* __restrict__ u,
                     const int* __restrict__ batch,  // int32 graph ids
                     float* __restrict__ out,        // (E,19)
                     int E, int B, int nTiles)
{
    extern __shared__ __align__(16) char smem[];
    float* st = (float*)smem;                               // [1024*19] staging
    float* su = (float*)(smem + ST_BYTES);                  // [B] u table

    const int tid = threadIdx.x;
    const int Bm1 = B - 1;
    const uint32_t st_sa = smem_u32(st);

    for (int i = tid; i < B; i += THREADS) su[i] = u[i];
    __syncthreads();

    const int stride = gridDim.x;

    // ---- software pipeline: raw input regs for the *current* tile ----
    float cs[PACKS][2], cd[PACKS][2], ca[PACKS][2];
    int   ci[PACKS][2];

    int tile = blockIdx.x;
    bool curFull = (tile < nTiles) && ((tile * TILE + TILE) <= E);
    if (curFull) {
        const int base = tile * TILE;
        #pragma unroll
        for (int c = 0; c < PACKS; c++) {
            const int g0 = base + c * (2 * THREADS) + tid;
            const int g1 = g0 + THREADS;
            cs[c][0] = src[g0];  cs[c][1] = src[g1];
            cd[c][0] = dest[g0]; cd[c][1] = dest[g1];
            ca[c][0] = ea[g0];   ca[c][1] = ea[g1];
            ci[c][0] = batch[g0]; ci[c][1] = batch[g1];
        }
    }

    for (; tile < nTiles; tile += stride) {
        const int base = tile * TILE;
        const int nextTile = tile + stride;
        const bool nextFull = (nextTile < nTiles) && ((nextTile * TILE + TILE) <= E);

        if (curFull) {
            // ---- consume raw regs into packed operands (u gathered now) ----
            ull S[PACKS], D[PACKS], A[PACKS], U[PACKS];
            #pragma unroll
            for (int c = 0; c < PACKS; c++) {
                int i0 = min(max(ci[c][0], 0), Bm1);
                int i1 = min(max(ci[c][1], 0), Bm1);
                S[c] = pack2(cs[c][0], cs[c][1]);
                D[c] = pack2(cd[c][0], cd[c][1]);
                A[c] = pack2(ca[c][0], ca[c][1]);
                U[c] = pack2(su[i0], su[i1]);
            }

            // ---- prefetch next tile's raw inputs (hidden under the MLP below) ----
            if (nextFull) {
                const int nbase = nextTile * TILE;
                #pragma unroll
                for (int c = 0; c < PACKS; c++) {
                    const int g0 = nbase + c * (2 * THREADS) + tid;
                    const int g1 = g0 + THREADS;
                    cs[c][0] = src[g0];  cs[c][1] = src[g1];
                    cd[c][0] = dest[g0]; cd[c][1] = dest[g1];
                    ca[c][0] = ea[g0];   ca[c][1] = ea[g1];
                    ci[c][0] = batch[g0]; ci[c][1] = batch[g1];
                }
            }

            // ---- stage 1: h = relu(x @ W1 + b1); weights from constant bank ----
            ull h[PACKS][HID];
            #pragma unroll
            for (int j = 0; j < HID; j++) {
                const ull w0 = cWt[j * 4 + 0];
                const ull w1 = cWt[j * 4 + 1];
                const ull w2 = cWt[j * 4 + 2];
                const ull w3 = cWt[j * 4 + 3];
                const ull bj = cWt[40 + j];
                #pragma unroll
                for (int c = 0; c < PACKS; c++) {
                    ull acc = ffma2(S[c], w0, bj);
                    acc = ffma2(D[c], w1, acc);
                    acc = ffma2(A[c], w2, acc);
                    acc = ffma2(U[c], w3, acc);
                    h[c][j] = relu2(acc);
                }
            }

            // ---- previous tile's bulk store must have finished READING st ----
            if (tid == 0) asm volatile("cp.async.bulk.wait_group.read 0;" ::: "memory");
            __syncthreads();

            // ---- stage 2: out = h @ W2 + b2; constants, even/odd dual chains ----
            #pragma unroll
            for (int k = 0; k < NOUT; k++) {
                const ull wk0 = cWt[50 + k * 10 + 0];
                const ull wk1 = cWt[50 + k * 10 + 1];
                const ull wk2 = cWt[50 + k * 10 + 2];
                const ull wk3 = cWt[50 + k * 10 + 3];
                const ull wk4 = cWt[50 + k * 10 + 4];
                const ull wk5 = cWt[50 + k * 10 + 5];
                const ull wk6 = cWt[50 + k * 10 + 6];
                const ull wk7 = cWt[50 + k * 10 + 7];
                const ull wk8 = cWt[50 + k * 10 + 8];
                const ull wk9 = cWt[50 + k * 10 + 9];
                const ull bk  = cWt[240 + k];
                #pragma unroll
                for (int c = 0; c < PACKS; c++) {
                    ull accA = ffma2(h[c][0], wk0, bk);
                    ull accB = ffma2(h[c][1], wk1, 0ULL);
                    accA = ffma2(h[c][2], wk2, accA);
                    accB = ffma2(h[c][3], wk3, accB);
                    accA = ffma2(h[c][4], wk4, accA);
                    accB = ffma2(h[c][5], wk5, accB);
                    accA = ffma2(h[c][6], wk6, accA);
                    accB = ffma2(h[c][7], wk7, accB);
                    accA = ffma2(h[c][8], wk8, accA);
                    accB = ffma2(h[c][9], wk9, accB);
                    ull acc = add2(accA, accB);
                    float lo, hi; unpack2(acc, lo, hi);
                    const int row0 = c * (2 * THREADS) + tid;
                    st[row0 * NOUT + k]             = lo;   // stride 19: conflict-free
                    st[(row0 + THREADS) * NOUT + k] = hi;
                }
            }
            __syncthreads();

            // ---- TMA bulk store: staging (contiguous) -> out tile (contiguous) ----
            if (tid == 0) {
                asm volatile("fence.proxy.async.shared::cta;" ::: "memory");
                asm volatile(
                    "cp.async.bulk.global.shared::cta.bulk_group [%0], [%1], %2;"
                    :: "l"(out + (size_t)base * NOUT), "r"(st_sa), "n"(ST_BYTES)
                    : "memory");
                asm volatile("cp.async.bulk.commit_group;" ::: "memory");
            }
        } else {
            // -------- tail tile (E % 1024 = 512 edges); loads its own inputs ----
            if (tid == 0) asm volatile("cp.async.bulk.wait_group.read 0;" ::: "memory");
            __syncthreads();
            const float* cf = (const float*)cWt;   // lo halves of packed pairs
            #pragma unroll
            for (int q = 0; q < 2 * PACKS; q++) {
                int row = tid + q * THREADS;
                int g = base + row;
                if (g < E) {
                    float s = src[g], d = dest[g], a = ea[g];
                    int bi = min(max(batch[g], 0), Bm1);
                    float uu = su[bi];
                    float h[HID];
                    #pragma unroll
                    for (int j = 0; j < HID; j++) {
                        float acc = cf[(40 + j) * 2];
                        acc = fmaf(s,  cf[(j * 4 + 0) * 2], acc);
                        acc = fmaf(d,  cf[(j * 4 + 1) * 2], acc);
                        acc = fmaf(a,  cf[(j * 4 + 2) * 2], acc);
                        acc = fmaf(uu, cf[(j * 4 + 3) * 2], acc);
                        h[j] = fmaxf(acc, 0.0f);
                    }
                    #pragma unroll
                    for (int k = 0; k < NOUT; k++) {
                        float acc = cf[(240 + k) * 2];
                        #pragma unroll
                        for (int j = 0; j < HID; j++)
                            acc = fmaf(h[j], cf[(50 + k * HID + j) * 2], acc);
                        st[row * NOUT + k] = acc;
                    }
                }
            }
            __syncthreads();
            int ve = E - base; if (ve > TILE) ve = TILE;
            size_t obase = (size_t)base * NOUT;
            for (int q = tid; q < ve * NOUT; q += THREADS) out[obase + q] = st[q];
            __syncthreads();

            if (nextFull) {
                const int nbase = nextTile * TILE;
                #pragma unroll
                for (int c = 0; c < PACKS; c++) {
                    const int g0 = nbase + c * (2 * THREADS) + tid;
                    const int g1 = g0 + THREADS;
                    cs[c][0] = src[g0];  cs[c][1] = src[g1];
                    cd[c][0] = dest[g0]; cd[c][1] = dest[g1];
                    ca[c][0] = ea[g0];   ca[c][1] = ea[g1];
                    ci[c][0] = batch[g0]; ci[c][1] = batch[g1];
                }
            }
        }
        curFull = nextFull;
    }

    // drain outstanding bulk stores before exit
    if (tid == 0) asm volatile("cp.async.bulk.wait_group 0;" ::: "memory");
}

extern "C" void kernel_launch(void* const* d_in, const int* in_sizes, int n_in,
                              void* d_out, int out_size)
{
    const float* src   = (const float*)d_in[0];
    const float* dest  = (const float*)d_in[1];
    const float* ea    = (const float*)d_in[2];
    const float* u     = (const float*)d_in[3];
    const int*   batch = (const int*)d_in[4];      // int32
    const float* W1    = (const float*)d_in[5];
    const float* b1    = (const float*)d_in[6];
    const float* W2    = (const float*)d_in[7];
    const float* b2    = (const float*)d_in[8];
    float* out = (float*)d_out;

    const int E = in_sizes[0];
    const int B = in_sizes[3];
    const int nTiles = (E + TILE - 1) / TILE;

    // 1) pack duplicated weight pairs into gWt (device global)
    pack_weights_kernel<<<1, 288>>>(W1, b1, W2, b2);

    // 2) D2D copy into the constant bank (capture-legal async memcpy node)
    void* gptr = nullptr;
    cudaGetSymbolAddress(&gptr, gWt);
    cudaMemcpyToSymbolAsync(cWt, gptr, NWT * sizeof(ull), 0,
                            cudaMemcpyDeviceToDevice);

    // 3) main kernel
    const int ub = (B * 4 + 15) & ~15;
    const int smemBytes = ST_BYTES + ub + 16;

    cudaFuncSetAttribute(edge_mlp_kernel,
                         cudaFuncAttributeMaxDynamicSharedMemorySize, smemBytes);

    int grid = nTiles < 296 ? nTiles : 296;   // 2 CTAs/SM resident, grid-stride
    if (grid < 1) grid = 1;

    edge_mlp_kernel<<<grid, THREADS, smemBytes>>>(
        src, dest, ea, u, batch, out, E, B, nTiles);
}